// round 1
// baseline (speedup 1.0000x reference)
#include <cuda_runtime.h>
#include <math.h>

// Problem dims (fixed by the dataset)
#define NMAX 20000
#define EMAX 200000
#define GMAX 128
#define DH   32

// Scratch (device globals; no allocation allowed)
__device__ float g_h0[NMAX * DH];
__device__ float g_h1[NMAX * DH];
__device__ float g_rh1[EMAX * DH];
__device__ float g_rh2[EMAX * DH];
__device__ float g_Gn[(size_t)NMAX * 1056];   // [N][33][32]: k=0..31 from w2, k=32 = bias part
__device__ float g_agg[NMAX * DH];
__device__ float g_pooled[GMAX * DH];

#define FULLMASK 0xffffffffu

__device__ __forceinline__ float lrelu(float v) { return v > 0.f ? v : 0.01f * v; }

// ---------------- Kernel A: h0 = lrelu(x @ nfc_w + nfc_b) -------------------
__global__ void k_node_in(const float* __restrict__ x, const float* __restrict__ w,
                          const float* __restrict__ b, float* __restrict__ h0, int N) {
    int warp = (blockIdx.x * blockDim.x + threadIdx.x) >> 5;
    int lane = threadIdx.x & 31;
    if (warp >= N) return;
    const float* xr = x + (size_t)warp * 64;
    float x0 = xr[lane];
    float x1 = xr[32 + lane];
    float acc = b[lane];
#pragma unroll
    for (int i = 0; i < 32; i++) {
        float xv = __shfl_sync(FULLMASK, x0, i);
        acc = fmaf(xv, w[i * 32 + lane], acc);
    }
#pragma unroll
    for (int i = 0; i < 32; i++) {
        float xv = __shfl_sync(FULLMASK, x1, i);
        acc = fmaf(xv, w[(32 + i) * 32 + lane], acc);
    }
    h0[warp * 32 + lane] = lrelu(acc);
}

// ---------------- Kernel B: rh_L = relu(edge_attr @ w1_L + b1_L), both layers
__global__ void k_edge_hidden(const float* __restrict__ ea,
                              const float* __restrict__ w1a, const float* __restrict__ b1a,
                              const float* __restrict__ w1b, const float* __restrict__ b1b,
                              float* __restrict__ rh1, float* __restrict__ rh2, int E) {
    int warp = (blockIdx.x * blockDim.x + threadIdx.x) >> 5;
    int lane = threadIdx.x & 31;
    if (warp >= E) return;
    float ev = (lane < 16) ? ea[(size_t)warp * 16 + lane] : 0.f;
    float a1 = b1a[lane];
    float a2 = b1b[lane];
#pragma unroll
    for (int j = 0; j < 16; j++) {
        float v = __shfl_sync(FULLMASK, ev, j);
        a1 = fmaf(v, w1a[j * 32 + lane], a1);
        a2 = fmaf(v, w1b[j * 32 + lane], a2);
    }
    rh1[warp * 32 + lane] = fmaxf(a1, 0.f);
    rh2[warp * 32 + lane] = fmaxf(a2, 0.f);
}

// ---------------- Kernel C: Gn[n][k][o] (k=0..32) and agg init (root + bias)
// Smem "W" table rows: 0..31 = w2 (k rows of [i*32+o]), 32 = b2, 33 = root.
// Thread t: o = t&31, kk = t>>5 (0..7). Slots s=0..4 -> k = kk + 8*s (k<34).
// Register-blocks NB=8 nodes to amortize smem reads.
#define NB 8
__global__ void k_precompute(const float* __restrict__ h,
                             const float* __restrict__ w2, const float* __restrict__ b2,
                             const float* __restrict__ root, const float* __restrict__ bias,
                             float* __restrict__ Gn, float* __restrict__ agg, int N) {
    extern __shared__ float sm[];
    float* Ws    = sm;            // 34*1024
    float* biass = sm + 34816;    // 32
    float* hs    = sm + 34848;    // NB*32

    int tid = threadIdx.x;
    // load the 34x1024 weight table once per CTA
    for (int idx = tid; idx < 34 * 1024; idx += 256) {
        float v;
        if (idx < 32768)      v = w2[idx];
        else if (idx < 33792) v = b2[idx - 32768];
        else                  v = root[idx - 33792];
        Ws[idx] = v;
    }
    if (tid < 32) biass[tid] = bias[tid];
    __syncthreads();

    int o  = tid & 31;
    int kk = tid >> 5;
    int k_[5];
#pragma unroll
    for (int s = 0; s < 5; s++) k_[s] = kk + 8 * s;

    int ngroups = (N + NB - 1) / NB;
    for (int grp = blockIdx.x; grp < ngroups; grp += gridDim.x) {
        int nbase = grp * NB;
        for (int j = tid; j < NB * 32; j += 256) {
            int n = nbase + (j >> 5);
            hs[j] = (n < N) ? h[(size_t)n * 32 + (j & 31)] : 0.f;
        }
        __syncthreads();

        float acc[5][NB];
#pragma unroll
        for (int s = 0; s < 5; s++)
#pragma unroll
            for (int nb = 0; nb < NB; nb++) acc[s][nb] = 0.f;

#pragma unroll 4
        for (int i = 0; i < 32; i++) {
            float w2v[5];
#pragma unroll
            for (int s = 0; s < 5; s++)
                w2v[s] = (k_[s] < 34) ? Ws[k_[s] * 1024 + i * 32 + o] : 0.f;
#pragma unroll
            for (int nb = 0; nb < NB; nb++) {
                float hv = hs[nb * 32 + i];
#pragma unroll
                for (int s = 0; s < 5; s++) acc[s][nb] = fmaf(hv, w2v[s], acc[s][nb]);
            }
        }

        // store
#pragma unroll
        for (int nb = 0; nb < NB; nb++) {
            int n = nbase + nb;
            if (n >= N) break;
#pragma unroll
            for (int s = 0; s < 5; s++) {
                int k = k_[s];
                if (k < 33) {
                    Gn[(size_t)n * 1056 + k * 32 + o] = acc[s][nb];
                } else if (k == 33) {
                    agg[(size_t)n * 32 + o] = acc[s][nb] + biass[o];
                }
            }
        }
        __syncthreads();
    }
}

// ---------------- Kernel D: per-edge message + scatter-add to agg[dst] ------
__global__ void k_edge_msg(const int* __restrict__ ei, const float* __restrict__ rh,
                           const float* __restrict__ Gn, float* __restrict__ agg, int E) {
    int warp = (blockIdx.x * blockDim.x + threadIdx.x) >> 5;
    int lane = threadIdx.x & 31;
    if (warp >= E) return;
    int src = ei[warp];
    int dst = ei[E + warp];
    float rv = rh[(size_t)warp * 32 + lane];
    const float* gp = Gn + (size_t)src * 1056;
    float msg = gp[1024 + lane];   // bias part (k=32 row)
#pragma unroll
    for (int k = 0; k < 32; k++) {
        float rk = __shfl_sync(FULLMASK, rv, k);
        msg = fmaf(rk, gp[k * 32 + lane], msg);
    }
    atomicAdd(&agg[(size_t)dst * 32 + lane], msg);
}

// ---------------- Kernel E1: h = lrelu(agg) ---------------------------------
__global__ void k_act(const float* __restrict__ agg, float* __restrict__ h, int total) {
    int idx = blockIdx.x * blockDim.x + threadIdx.x;
    if (idx >= total) return;
    h[idx] = lrelu(agg[idx]);
}

// ---------------- zero pooled ------------------------------------------------
__global__ void k_zero(float* __restrict__ p, int total) {
    int idx = blockIdx.x * blockDim.x + threadIdx.x;
    if (idx < total) p[idx] = 0.f;
}

// ---------------- Kernel E2: atom_embs = lrelu(agg); pool into graphs -------
__global__ void k_act_pool(const float* __restrict__ agg, const int* __restrict__ batch,
                           float* __restrict__ atom_out, float* __restrict__ pooled, int N) {
    int idx = blockIdx.x * blockDim.x + threadIdx.x;
    if (idx >= N * 32) return;
    int n = idx >> 5;
    int o = idx & 31;
    float v = lrelu(agg[idx]);
    atom_out[idx] = v;
    atomicAdd(&pooled[batch[n] * 32 + o], v);
}

// ---------------- Kernel F: normalize pooled rows + final fc ----------------
__global__ void k_final(const float* __restrict__ pooled, const float* __restrict__ fcw,
                        const float* __restrict__ fcb, float* __restrict__ out, int G) {
    int warp = (blockIdx.x * blockDim.x + threadIdx.x) >> 5;
    int lane = threadIdx.x & 31;
    if (warp >= G) return;
    float p = pooled[warp * 32 + lane];
    float ss = p * p;
#pragma unroll
    for (int off = 16; off > 0; off >>= 1) ss += __shfl_xor_sync(FULLMASK, ss, off);
    float nrm = sqrtf(ss);
    float d = fmaxf(nrm, 1e-12f);
    float pn = p / d;
    float acc = fcb[lane];
#pragma unroll
    for (int j = 0; j < 32; j++) {
        float pv = __shfl_sync(FULLMASK, pn, j);
        acc = fmaf(pv, fcw[j * 32 + lane], acc);
    }
    out[warp * 32 + lane] = acc;
}

extern "C" void kernel_launch(void* const* d_in, const int* in_sizes, int n_in,
                              void* d_out, int out_size) {
    const float* x        = (const float*)d_in[0];
    const int*   ei       = (const int*)  d_in[1];
    const float* ea       = (const float*)d_in[2];
    const int*   batch    = (const int*)  d_in[3];
    // d_in[4] = num_graphs (scalar, known = 128)
    const float* nfc_w    = (const float*)d_in[5];
    const float* nfc_b    = (const float*)d_in[6];
    const float* e1w1     = (const float*)d_in[7];
    const float* e1b1     = (const float*)d_in[8];
    const float* e1w2     = (const float*)d_in[9];
    const float* e1b2     = (const float*)d_in[10];
    const float* root1    = (const float*)d_in[11];
    const float* bias1    = (const float*)d_in[12];
    const float* e2w1     = (const float*)d_in[13];
    const float* e2b1     = (const float*)d_in[14];
    const float* e2w2     = (const float*)d_in[15];
    const float* e2b2     = (const float*)d_in[16];
    const float* root2    = (const float*)d_in[17];
    const float* bias2    = (const float*)d_in[18];
    const float* fcw      = (const float*)d_in[19];
    const float* fcb      = (const float*)d_in[20];

    int N = in_sizes[0] / 64;
    int E = in_sizes[2] / 16;
    const int G = GMAX;

    float* outp = (float*)d_out;                 // [G,32]
    float* atom_out = (float*)d_out + G * 32;    // [N,32]

    float *h0, *h1, *rh1, *rh2, *Gn, *agg, *pooled;
    cudaGetSymbolAddress((void**)&h0,     g_h0);
    cudaGetSymbolAddress((void**)&h1,     g_h1);
    cudaGetSymbolAddress((void**)&rh1,    g_rh1);
    cudaGetSymbolAddress((void**)&rh2,    g_rh2);
    cudaGetSymbolAddress((void**)&Gn,     g_Gn);
    cudaGetSymbolAddress((void**)&agg,    g_agg);
    cudaGetSymbolAddress((void**)&pooled, g_pooled);

    // dynamic smem for precompute kernel: (34*1024 + 32 + NB*32) floats
    const int smemC = (34 * 1024 + 32 + NB * 32) * sizeof(float);
    cudaFuncSetAttribute(k_precompute, cudaFuncAttributeMaxDynamicSharedMemorySize, smemC);

    // A: input node transform
    k_node_in<<<(N + 7) / 8, 256>>>(x, nfc_w, nfc_b, h0, N);
    // B: both edge-MLP hidden layers
    k_edge_hidden<<<(E + 7) / 8, 256>>>(ea, e1w1, e1b1, e2w1, e2b1, rh1, rh2, E);

    // ---- layer 1 ----
    k_precompute<<<152, 256, smemC>>>(h0, e1w2, e1b2, root1, bias1, Gn, agg, N);
    k_edge_msg<<<(E + 7) / 8, 256>>>(ei, rh1, Gn, agg, E);
    k_act<<<(N * 32 + 255) / 256, 256>>>(agg, h1, N * 32);

    // ---- layer 2 ----
    k_precompute<<<152, 256, smemC>>>(h1, e2w2, e2b2, root2, bias2, Gn, agg, N);
    k_edge_msg<<<(E + 7) / 8, 256>>>(ei, rh2, Gn, agg, E);

    // pooling + outputs
    k_zero<<<(G * 32 + 255) / 256, 256>>>(pooled, G * 32);
    k_act_pool<<<(N * 32 + 255) / 256, 256>>>(agg, batch, atom_out, pooled, N);
    k_final<<<(G + 3) / 4, 128>>>(pooled, fcw, fcb, outp, G);
}